// round 11
// baseline (speedup 1.0000x reference)
#include <cuda_runtime.h>
#include <mma.h>
#include <cstddef>
#include <cstdint>

using namespace nvcuda;

// Problem constants (fixed by setup_inputs)
constexpr int D      = 64;
constexpr int N      = 128;
constexpr int NSTEPS = 16;

constexpr int MROWS = D * D;       // 4096 = (i,a)
constexpr int NCOLS = N * D;       // 8192 = (n,b)

// ---------------- device scratch (no allocations allowed) ----------------
__device__ __align__(16) float g_R[NSTEPS][D * D];  // [s][i*64+a] = R_{15-s}[a][i]
__device__ __align__(16) float g_X[NSTEPS][N * D];  // x_s, s = 0..15
// 3xTF32 split operands for the big GEMM
__device__ __align__(16) float g_Ahi[MROWS * NSTEPS];   // A[r][s], r=(i,a)
__device__ __align__(16) float g_Alo[MROWS * NSTEPS];
__device__ __align__(16) float g_Bhi[NSTEPS * NCOLS];   // B[s][c], c=(n,b)
__device__ __align__(16) float g_Blo[NSTEPS * NCOLS];

// KPREP: direct row-wise simulation of BOTH systems in one launch.
//   rows 0..127   : state rows (x0, v0)            -> g_X[t], traj frames
//   rows 128..191 : propagator rows a = row-128,
//                   X0 = dt^2*e_a, V0 = dt*e_a     -> X_k = R_k, stored transposed
__global__ void __launch_bounds__(128) kprep(const float* __restrict__ x0,
                                             const float* __restrict__ v0,
                                             const float* __restrict__ W,
                                             float* __restrict__ out) {
    __shared__ float sX[4][D];
    const int tid = threadIdx.x;
    const int w   = tid >> 5;                  // warp = local row
    const int l   = tid & 31;
    const int row = blockIdx.x * 4 + w;        // 0..191
    const int c0  = 2 * l;
    const float dt = 0.01f;
    const bool is_state = (row < N);
    const int a = row - N;                     // propagator row index (if !is_state)

    float mA[D], mB[D];
    {
        const float4* wa = (const float4*)(W + (size_t)c0 * D);
        const float4* wb = (const float4*)(W + (size_t)(c0 + 1) * D);
#pragma unroll
        for (int q = 0; q < 16; q++) {
            float4 va = wa[q], vb = wb[q];
            const int k = 4 * q;
            mA[k+0] = va.x - ((k+0) == c0     ? 1.0f : 0.0f);
            mA[k+1] = va.y - ((k+1) == c0     ? 1.0f : 0.0f);
            mA[k+2] = va.z - ((k+2) == c0     ? 1.0f : 0.0f);
            mA[k+3] = va.w - ((k+3) == c0     ? 1.0f : 0.0f);
            mB[k+0] = vb.x - ((k+0) == c0 + 1 ? 1.0f : 0.0f);
            mB[k+1] = vb.y - ((k+1) == c0 + 1 ? 1.0f : 0.0f);
            mB[k+2] = vb.z - ((k+2) == c0 + 1 ? 1.0f : 0.0f);
            mB[k+3] = vb.w - ((k+3) == c0 + 1 ? 1.0f : 0.0f);
        }
    }

    float2 xl, vl;
    if (is_state) {
        xl = *(const float2*)(x0 + (size_t)row * D + c0);
        vl = *(const float2*)(v0 + (size_t)row * D + c0);
    } else {
        xl = make_float2(c0 == a ? dt * dt : 0.0f, (c0 + 1) == a ? dt * dt : 0.0f);
        vl = make_float2(c0 == a ? dt      : 0.0f, (c0 + 1) == a ? dt      : 0.0f);
    }

    if (is_state) {
        *(float2*)&g_X[0][row * D + c0] = xl;                 // x_0
        *(float2*)(out + (size_t)row * D + c0) = xl;          // traj frame 0
    } else {
        g_R[15][c0 * D + a]       = xl.x;                     // R_0 transposed
        g_R[15][(c0 + 1) * D + a] = xl.y;
    }

    *(float2*)&sX[w][c0] = xl;
    __syncwarp();

#pragma unroll 1
    for (int t = 1; t <= NSTEPS; t++) {
        float2 y0 = make_float2(0.0f, 0.0f);
        float2 y1 = make_float2(0.0f, 0.0f);
#pragma unroll
        for (int k = 0; k < D; k += 2) {
            float xk0 = sX[w][k], xk1 = sX[w][k + 1];
            y0.x += xk0 * mA[k];     y0.y += xk0 * mB[k];
            y1.x += xk1 * mA[k + 1]; y1.y += xk1 * mB[k + 1];
        }
        float2 y = make_float2(y0.x + y1.x, y0.y + y1.y);
        vl.x += dt * y.x;  vl.y += dt * y.y;
        xl.x += dt * vl.x; xl.y += dt * vl.y;
        __syncwarp();
        *(float2*)&sX[w][c0] = xl;
        __syncwarp();

        if (is_state) {
            if (t < NSTEPS)
                *(float2*)&g_X[t][row * D + c0] = xl;
            if ((t & 3) == 0) {
                float* o = out + (size_t)(t >> 2) * (N * D) + (size_t)row * D + c0;
                *(float2*)o = xl;
            }
        } else if (t < NSTEPS) {
            g_R[15 - t][c0 * D + a]       = xl.x;
            g_R[15 - t][(c0 + 1) * D + a] = xl.y;
        }
    }
}

__device__ __forceinline__ float tf32r(float f) {
    unsigned r;
    asm("cvt.rna.tf32.f32 %0, %1;" : "=r"(r) : "f"(f));
    return __uint_as_float(r);
}

// KSPLIT: build 3xTF32 operands.
//  A[r][s] = g_R[s][r] (transpose), split hi/lo.  (65536 elements)
//  B[s][c] = g_X[s][c] (copy),      split hi/lo.  (131072 elements)
__global__ void __launch_bounds__(256) ksplit() {
    int idx = blockIdx.x * 256 + threadIdx.x;
    if (idx < MROWS * NSTEPS) {
        const int r = idx >> 4, s = idx & 15;
        const float f  = g_R[s][r];
        const float hi = tf32r(f);
        g_Ahi[r * NSTEPS + s] = hi;
        g_Alo[r * NSTEPS + s] = tf32r(f - hi);
    } else {
        idx -= MROWS * NSTEPS;
        const int s = idx >> 13, c = idx & (NCOLS - 1);
        const float f  = g_X[s][c];
        const float hi = tf32r(f);
        g_Bhi[s * NCOLS + c] = hi;
        g_Blo[s * NCOLS + c] = tf32r(f - hi);
    }
}

// K4: one GEMM  C[(i,a)][(n,b)] = sum_s A[(i,a)][s] * B[s][(n,b)]
// via wmma 16x16x8 tf32, 3xTF32 (hi*hi + hi*lo + lo*hi).
// Block tile 128(M) x 128(N), 8 warps (4M x 2N), warp tile 32 x 64.
// Each 16x16 C tile = jac[n][i][a0..a0+16][b0..b0+16]  (ldm = 64, row-major).
__global__ void __launch_bounds__(256) k4_jac(float* __restrict__ jac) {
    const int bid = blockIdx.x;
    const int bm = bid & 31;          // 32 M-blocks
    const int bn = bid >> 5;          // 64 N-blocks
    const int wid = threadIdx.x >> 5;
    const int wm = wid & 3, wn = wid >> 2;
    const int m0 = bm * 128 + wm * 32;
    const int n0 = bn * 128 + wn * 64;

    wmma::fragment<wmma::matrix_a, 16, 16, 8, wmma::precision::tf32,
                   wmma::row_major> ah[2][2], al[2][2];
#pragma unroll
    for (int mt = 0; mt < 2; mt++)
#pragma unroll
        for (int ks = 0; ks < 2; ks++) {
            const float* p = g_Ahi + (size_t)(m0 + mt * 16) * NSTEPS + ks * 8;
            const float* q = g_Alo + (size_t)(m0 + mt * 16) * NSTEPS + ks * 8;
            wmma::load_matrix_sync(ah[mt][ks], p, NSTEPS);
            wmma::load_matrix_sync(al[mt][ks], q, NSTEPS);
        }

#pragma unroll
    for (int nt = 0; nt < 4; nt++) {
        const int c = n0 + nt * 16;
        wmma::fragment<wmma::matrix_b, 16, 16, 8, wmma::precision::tf32,
                       wmma::row_major> bh[2], bl[2];
#pragma unroll
        for (int ks = 0; ks < 2; ks++) {
            wmma::load_matrix_sync(bh[ks], g_Bhi + (size_t)(ks * 8) * NCOLS + c, NCOLS);
            wmma::load_matrix_sync(bl[ks], g_Blo + (size_t)(ks * 8) * NCOLS + c, NCOLS);
        }
#pragma unroll
        for (int mt = 0; mt < 2; mt++) {
            wmma::fragment<wmma::accumulator, 16, 16, 8, float> acc;
            wmma::fill_fragment(acc, 0.0f);
#pragma unroll
            for (int ks = 0; ks < 2; ks++) {
                wmma::mma_sync(acc, ah[mt][ks], bh[ks], acc);
                wmma::mma_sync(acc, ah[mt][ks], bl[ks], acc);
                wmma::mma_sync(acc, al[mt][ks], bh[ks], acc);
            }
            const int r = m0 + mt * 16;
            // jac offset: ((n*64 + i)*64 + a)*64 + b ; r=(i,a), c=(n,b)
            const size_t off = (size_t)(c >> 6) * (64 * 64 * 64)
                             + (size_t)(r >> 6) * (64 * 64)
                             + (size_t)(r & 63) * 64
                             + (size_t)(c & 63);
            wmma::store_matrix_sync(jac + off, acc, 64, wmma::mem_row_major);
        }
    }
}

extern "C" void kernel_launch(void* const* d_in, const int* in_sizes, int n_in,
                              void* d_out, int out_size) {
    const float* x0 = (const float*)d_in[0];
    const float* v0 = (const float*)d_in[1];
    const float* W  = (const float*)d_in[2];
    float* out = (float*)d_out;
    // output = [traj (frames x N x D)] then [jac (N x D x D x D)]
    float* jac = out + ((size_t)out_size - (size_t)N * D * D * D);

    kprep<<<48, 128>>>(x0, v0, W, out);
    ksplit<<<(MROWS * NSTEPS + NSTEPS * NCOLS) / 256, 256>>>();
    k4_jac<<<2048, 256>>>(jac);
}

// round 12
// speedup vs baseline: 1.1583x; 1.1583x over previous
#include <cuda_runtime.h>
#include <mma.h>
#include <cstddef>
#include <cstdint>

using namespace nvcuda;

// Problem constants (fixed by setup_inputs)
constexpr int D      = 64;
constexpr int N      = 128;
constexpr int NSTEPS = 16;

constexpr int MROWS = D * D;       // 4096 = (i,a)
constexpr int NCOLS = N * D;       // 8192 = (n,b)

// ---------------- device scratch (no allocations allowed) ----------------
// 3xTF32 split operands for the big GEMM (written directly by kprep)
__device__ __align__(16) float g_Ahi[MROWS * NSTEPS];   // A[r][s], r=(i,a)
__device__ __align__(16) float g_Alo[MROWS * NSTEPS];
__device__ __align__(16) float g_Bhi[NSTEPS * NCOLS];   // B[s][c], c=(n,b)
__device__ __align__(16) float g_Blo[NSTEPS * NCOLS];

__device__ __forceinline__ float tf32r(float f) {
    unsigned r;
    asm("cvt.rna.tf32.f32 %0, %1;" : "=r"(r) : "f"(f));
    return __uint_as_float(r);
}

// KPREP: direct row-wise simulation of BOTH systems, writing tf32 hi/lo
// operands directly (no separate split pass).
//   rows 0..127   : state rows (x0, v0)  -> B[s][(n,b)] splits + traj frames
//   rows 128..191 : propagator rows a:  X0 = dt^2*e_a, V0 = dt*e_a
//                   -> A[(i,a)][15-t] splits
// 2 rows per 128-thread block; 64 lanes per row, one column per lane;
// M column (64 floats) in registers. M[k][c] = W[c][k] - delta(k,c).
__global__ void __launch_bounds__(128) kprep(const float* __restrict__ x0,
                                             const float* __restrict__ v0,
                                             const float* __restrict__ W,
                                             float* __restrict__ out) {
    __shared__ float sX[2][D];
    const int tid = threadIdx.x;
    const int w   = tid >> 5;
    const int l   = tid & 31;
    const int rl  = w >> 1;                    // local row 0..1
    const int row = blockIdx.x * 2 + rl;       // 0..191
    const int c   = ((w & 1) << 5) | l;        // column 0..63
    const float dt = 0.01f;
    const bool is_state = (row < N);
    const int a = row - N;

    // This lane's M column in registers.
    float m[D];
    {
        const float4* wr = (const float4*)(W + (size_t)c * D);
#pragma unroll
        for (int q = 0; q < 16; q++) {
            float4 v4 = wr[q];
            const int k = 4 * q;
            m[k+0] = v4.x - ((k+0) == c ? 1.0f : 0.0f);
            m[k+1] = v4.y - ((k+1) == c ? 1.0f : 0.0f);
            m[k+2] = v4.z - ((k+2) == c ? 1.0f : 0.0f);
            m[k+3] = v4.w - ((k+3) == c ? 1.0f : 0.0f);
        }
    }

    float x, v;
    if (is_state) {
        x = x0[(size_t)row * D + c];
        v = v0[(size_t)row * D + c];
    } else {
        x = (c == a) ? dt * dt : 0.0f;
        v = (c == a) ? dt : 0.0f;
    }

    // t = 0 outputs.
    if (is_state) {
        out[(size_t)row * D + c] = x;                        // traj frame 0
        const float hi = tf32r(x);
        g_Bhi[(size_t)row * D + c] = hi;                     // s=0
        g_Blo[(size_t)row * D + c] = tf32r(x - hi);
    } else {
        const float hi = tf32r(x);
        const size_t r16 = ((size_t)c * D + a) * NSTEPS + 15;
        g_Ahi[r16] = hi;
        g_Alo[r16] = tf32r(x - hi);
    }

    sX[rl][c] = x;
    __syncthreads();

#pragma unroll 1
    for (int t = 1; t <= NSTEPS; t++) {
        float y0 = 0.0f, y1 = 0.0f, y2 = 0.0f, y3 = 0.0f;
#pragma unroll
        for (int k = 0; k < D; k += 4) {
            y0 += sX[rl][k]     * m[k];
            y1 += sX[rl][k + 1] * m[k + 1];
            y2 += sX[rl][k + 2] * m[k + 2];
            y3 += sX[rl][k + 3] * m[k + 3];
        }
        v += dt * ((y0 + y1) + (y2 + y3));
        x += dt * v;
        __syncthreads();
        sX[rl][c] = x;
        __syncthreads();

        if (is_state) {
            if (t < NSTEPS) {
                const float hi = tf32r(x);
                g_Bhi[(size_t)t * NCOLS + (size_t)row * D + c] = hi;
                g_Blo[(size_t)t * NCOLS + (size_t)row * D + c] = tf32r(x - hi);
            }
            if ((t & 3) == 0)
                out[(size_t)(t >> 2) * NCOLS + (size_t)row * D + c] = x;
        } else if (t < NSTEPS) {
            const float hi = tf32r(x);
            const size_t rs = ((size_t)c * D + a) * NSTEPS + (15 - t);
            g_Ahi[rs] = hi;
            g_Alo[rs] = tf32r(x - hi);
        }
    }
}

// K4: C[(i,a)][(n,b)] = sum_s A[(i,a)][s] * B[s][(n,b)]  — one 4096x8192x16
// GEMM via wmma 16x16x8 tf32 with 3xTF32 (hi*hi + hi*lo + lo*hi).
// Block tile 128(M) x 128(N); A/B tiles staged in smem with coalesced float4
// LDGs, fragments loaded from smem (padded ldm). 8 warps = 4M x 2N, warp tile
// 32 x 64. Each 16x16 C tile stores directly into jac (ldm = 64, row-major).
constexpr int ALD = 20;    // smem ldm for A (16 + pad, multiple of 4)
constexpr int BLD = 132;   // smem ldm for B (128 + pad, multiple of 4)

__global__ void __launch_bounds__(256) k4_jac(float* __restrict__ jac) {
    __shared__ __align__(16) float sAh[128 * ALD];   // 10 KB
    __shared__ __align__(16) float sAl[128 * ALD];
    __shared__ __align__(16) float sBh[16 * BLD];    // 8.25 KB
    __shared__ __align__(16) float sBl[16 * BLD];
    const int tid = threadIdx.x, bid = blockIdx.x;
    const int m0 = (bid & 31) * 128;   // 32 M-blocks
    const int n0 = (bid >> 5) * 128;   // 64 N-blocks

    // Stage A (128 rows x 16) and B (16 rows x 128), hi+lo, coalesced.
#pragma unroll
    for (int v = tid; v < 512; v += 256) {
        {   // A: contiguous global region [m0*16, m0*16+2048)
            const int row = v >> 2, q = (v & 3) << 2;
            *(float4*)&sAh[row * ALD + q] =
                *(const float4*)&g_Ahi[(size_t)(m0 + row) * NSTEPS + q];
            *(float4*)&sAl[row * ALD + q] =
                *(const float4*)&g_Alo[(size_t)(m0 + row) * NSTEPS + q];
        }
        {   // B: 16 rows of 128 floats at stride NCOLS
            const int s = v >> 5, q = (v & 31) << 2;
            *(float4*)&sBh[s * BLD + q] =
                *(const float4*)&g_Bhi[(size_t)s * NCOLS + n0 + q];
            *(float4*)&sBl[s * BLD + q] =
                *(const float4*)&g_Blo[(size_t)s * NCOLS + n0 + q];
        }
    }
    __syncthreads();

    const int wid = tid >> 5;
    const int wm = wid & 3, wn = wid >> 2;

    wmma::fragment<wmma::matrix_a, 16, 16, 8, wmma::precision::tf32,
                   wmma::row_major> ah[2][2], al[2][2];
#pragma unroll
    for (int mt = 0; mt < 2; mt++)
#pragma unroll
        for (int ks = 0; ks < 2; ks++) {
            const int ro = (wm * 32 + mt * 16) * ALD + ks * 8;
            wmma::load_matrix_sync(ah[mt][ks], &sAh[ro], ALD);
            wmma::load_matrix_sync(al[mt][ks], &sAl[ro], ALD);
        }

#pragma unroll
    for (int nt = 0; nt < 4; nt++) {
        const int cl = wn * 64 + nt * 16;
        wmma::fragment<wmma::matrix_b, 16, 16, 8, wmma::precision::tf32,
                       wmma::row_major> bh[2], bl[2];
#pragma unroll
        for (int ks = 0; ks < 2; ks++) {
            wmma::load_matrix_sync(bh[ks], &sBh[(ks * 8) * BLD + cl], BLD);
            wmma::load_matrix_sync(bl[ks], &sBl[(ks * 8) * BLD + cl], BLD);
        }
#pragma unroll
        for (int mt = 0; mt < 2; mt++) {
            wmma::fragment<wmma::accumulator, 16, 16, 8, float> acc;
            wmma::fill_fragment(acc, 0.0f);
#pragma unroll
            for (int ks = 0; ks < 2; ks++) {
                wmma::mma_sync(acc, ah[mt][ks], bh[ks], acc);
                wmma::mma_sync(acc, ah[mt][ks], bl[ks], acc);
                wmma::mma_sync(acc, al[mt][ks], bh[ks], acc);
            }
            const int r = m0 + wm * 32 + mt * 16;   // (i,a)
            const int c = n0 + cl;                  // (n,b)
            // jac offset: ((n*64 + i)*64 + a)*64 + b
            const size_t off = (size_t)(c >> 6) * (64 * 64 * 64)
                             + (size_t)(r >> 6) * (64 * 64)
                             + (size_t)(r & 63) * 64
                             + (size_t)(c & 63);
            wmma::store_matrix_sync(jac + off, acc, 64, wmma::mem_row_major);
        }
    }
}

extern "C" void kernel_launch(void* const* d_in, const int* in_sizes, int n_in,
                              void* d_out, int out_size) {
    const float* x0 = (const float*)d_in[0];
    const float* v0 = (const float*)d_in[1];
    const float* W  = (const float*)d_in[2];
    float* out = (float*)d_out;
    // output = [traj (frames x N x D)] then [jac (N x D x D x D)]
    float* jac = out + ((size_t)out_size - (size_t)N * D * D * D);

    kprep<<<96, 128>>>(x0, v0, W, out);
    k4_jac<<<2048, 256>>>(jac);
}

// round 13
// speedup vs baseline: 1.4836x; 1.2808x over previous
#include <cuda_runtime.h>
#include <cuda_bf16.h>
#include <mma.h>
#include <cstddef>
#include <cstdint>

using namespace nvcuda;

// Problem constants (fixed by setup_inputs)
constexpr int D      = 64;
constexpr int N      = 128;
constexpr int NSTEPS = 16;

constexpr int MROWS = D * D;       // 4096 = (i,a)
constexpr int NCOLS = N * D;       // 8192 = (n,b)

// ---------------- device scratch (no allocations allowed) ----------------
// Split-bf16 operands (a ~= a0 + a1, 16 effective mantissa bits)
__device__ __align__(16) __nv_bfloat16 g_A0[MROWS * NSTEPS];   // A[r][s], r=(i,a)
__device__ __align__(16) __nv_bfloat16 g_A1[MROWS * NSTEPS];
__device__ __align__(16) __nv_bfloat16 g_B0[NSTEPS * NCOLS];   // B[s][c], c=(n,b)
__device__ __align__(16) __nv_bfloat16 g_B1[NSTEPS * NCOLS];

__device__ __forceinline__ void bf16split(float f, __nv_bfloat16& h0,
                                          __nv_bfloat16& h1) {
    h0 = __float2bfloat16_rn(f);
    h1 = __float2bfloat16_rn(f - __bfloat162float(h0));
}

// KPREP: direct row-wise simulation of BOTH systems, writing split-bf16
// operands directly.
//   rows 0..127   : state rows (x0, v0)  -> B[s][(n,b)] splits + traj frames
//   rows 128..191 : propagator rows a:  X0 = dt^2*e_a, V0 = dt*e_a
//                   -> A[(i,a)][15-t] splits
// 2 rows per 128-thread block; one column per lane; M column in registers.
// M[k][c] = W[c][k] - delta(k,c)  (row-vector convention: f = x*M).
__global__ void __launch_bounds__(128) kprep(const float* __restrict__ x0,
                                             const float* __restrict__ v0,
                                             const float* __restrict__ W,
                                             float* __restrict__ out) {
    __shared__ float sX[2][D];
    const int tid = threadIdx.x;
    const int w   = tid >> 5;
    const int l   = tid & 31;
    const int rl  = w >> 1;                    // local row 0..1
    const int row = blockIdx.x * 2 + rl;       // 0..191
    const int c   = ((w & 1) << 5) | l;        // column 0..63
    const float dt = 0.01f;
    const bool is_state = (row < N);
    const int a = row - N;

    float m[D];
    {
        const float4* wr = (const float4*)(W + (size_t)c * D);
#pragma unroll
        for (int q = 0; q < 16; q++) {
            float4 v4 = wr[q];
            const int k = 4 * q;
            m[k+0] = v4.x - ((k+0) == c ? 1.0f : 0.0f);
            m[k+1] = v4.y - ((k+1) == c ? 1.0f : 0.0f);
            m[k+2] = v4.z - ((k+2) == c ? 1.0f : 0.0f);
            m[k+3] = v4.w - ((k+3) == c ? 1.0f : 0.0f);
        }
    }

    float x, v;
    if (is_state) {
        x = x0[(size_t)row * D + c];
        v = v0[(size_t)row * D + c];
    } else {
        x = (c == a) ? dt * dt : 0.0f;
        v = (c == a) ? dt : 0.0f;
    }

    // t = 0 outputs.
    if (is_state) {
        out[(size_t)row * D + c] = x;                        // traj frame 0
        bf16split(x, g_B0[(size_t)row * D + c], g_B1[(size_t)row * D + c]);
    } else {
        const size_t r16 = ((size_t)c * D + a) * NSTEPS + 15;
        bf16split(x, g_A0[r16], g_A1[r16]);
    }

    sX[rl][c] = x;
    __syncthreads();

#pragma unroll 1
    for (int t = 1; t <= NSTEPS; t++) {
        float y0 = 0.0f, y1 = 0.0f, y2 = 0.0f, y3 = 0.0f;
#pragma unroll
        for (int k = 0; k < D; k += 4) {
            y0 += sX[rl][k]     * m[k];
            y1 += sX[rl][k + 1] * m[k + 1];
            y2 += sX[rl][k + 2] * m[k + 2];
            y3 += sX[rl][k + 3] * m[k + 3];
        }
        v += dt * ((y0 + y1) + (y2 + y3));
        x += dt * v;
        __syncthreads();
        sX[rl][c] = x;
        __syncthreads();

        if (is_state) {
            if (t < NSTEPS) {
                const size_t o = (size_t)t * NCOLS + (size_t)row * D + c;
                bf16split(x, g_B0[o], g_B1[o]);
            }
            if ((t & 3) == 0)
                out[(size_t)(t >> 2) * NCOLS + (size_t)row * D + c] = x;
        } else if (t < NSTEPS) {
            const size_t rs = ((size_t)c * D + a) * NSTEPS + (15 - t);
            bf16split(x, g_A0[rs], g_A1[rs]);
        }
    }
}

// K4: C[(i,a)][(n,b)] = sum_s A[(i,a)][s] * B[s][(n,b)]  — one 4096x8192x16
// GEMM via wmma 16x16x16 bf16, 3-pass split-bf16 (a0b0 + a0b1 + a1b0;
// dropped a1b1 ~ 2^-16 relative). The whole K=16 fits in ONE wmma per pass:
// 6 HMMA.16816 per 16x16 output tile vs 12 HMMA.1688 for 3xTF32, and all
// operand fragments are half the bytes.
// Block tile 128(M) x 128(N); A/B staged in smem (coalesced float4 LDG);
// 8 warps = 4M x 2N, warp tile 32 x 64. C tiles store directly into jac.
constexpr int ALD = 24;    // bf16 smem ldm for A (16 + 8 pad; mult of 8)
constexpr int BLD = 136;   // bf16 smem ldm for B (128 + 8 pad; mult of 8)

__global__ void __launch_bounds__(256) k4_jac(float* __restrict__ jac) {
    __shared__ __align__(16) __nv_bfloat16 sA0[128 * ALD];   // 6 KB
    __shared__ __align__(16) __nv_bfloat16 sA1[128 * ALD];
    __shared__ __align__(16) __nv_bfloat16 sB0[16 * BLD];    // 4.25 KB
    __shared__ __align__(16) __nv_bfloat16 sB1[16 * BLD];
    const int tid = threadIdx.x, bid = blockIdx.x;
    const int m0 = (bid & 31) * 128;   // 32 M-blocks
    const int n0 = (bid >> 5) * 128;   // 64 N-blocks

    // Stage A (128 rows x 16 bf16) and B (16 rows x 128 bf16), both splits.
    {
        // A: 256 float4-chunks per array (2 chunks of 8 bf16 per row)
        const int row = tid >> 1, q = (tid & 1) << 3;
        *(float4*)&sA0[row * ALD + q] =
            *(const float4*)&g_A0[(size_t)(m0 + row) * NSTEPS + q];
        *(float4*)&sA1[row * ALD + q] =
            *(const float4*)&g_A1[(size_t)(m0 + row) * NSTEPS + q];
        // B: 256 chunks per array (16 chunks of 8 bf16 per s-row)
        const int s = tid >> 4, bq = (tid & 15) << 3;
        *(float4*)&sB0[s * BLD + bq] =
            *(const float4*)&g_B0[(size_t)s * NCOLS + n0 + bq];
        *(float4*)&sB1[s * BLD + bq] =
            *(const float4*)&g_B1[(size_t)s * NCOLS + n0 + bq];
    }
    __syncthreads();

    const int wid = tid >> 5;
    const int wm = wid & 3, wn = wid >> 2;

    wmma::fragment<wmma::matrix_a, 16, 16, 16, __nv_bfloat16,
                   wmma::row_major> a0f[2], a1f[2];
#pragma unroll
    for (int mt = 0; mt < 2; mt++) {
        const int ro = (wm * 32 + mt * 16) * ALD;
        wmma::load_matrix_sync(a0f[mt], &sA0[ro], ALD);
        wmma::load_matrix_sync(a1f[mt], &sA1[ro], ALD);
    }

#pragma unroll
    for (int nt = 0; nt < 4; nt++) {
        const int cl = wn * 64 + nt * 16;
        wmma::fragment<wmma::matrix_b, 16, 16, 16, __nv_bfloat16,
                       wmma::row_major> b0f, b1f;
        wmma::load_matrix_sync(b0f, &sB0[cl], BLD);
        wmma::load_matrix_sync(b1f, &sB1[cl], BLD);
#pragma unroll
        for (int mt = 0; mt < 2; mt++) {
            wmma::fragment<wmma::accumulator, 16, 16, 16, float> acc;
            wmma::fill_fragment(acc, 0.0f);
            wmma::mma_sync(acc, a0f[mt], b0f, acc);
            wmma::mma_sync(acc, a0f[mt], b1f, acc);
            wmma::mma_sync(acc, a1f[mt], b0f, acc);
            const int r = m0 + wm * 32 + mt * 16;   // (i,a)
            const int c = n0 + cl;                  // (n,b)
            // jac offset: ((n*64 + i)*64 + a)*64 + b
            const size_t off = (size_t)(c >> 6) * (64 * 64 * 64)
                             + (size_t)(r >> 6) * (64 * 64)
                             + (size_t)(r & 63) * 64
                             + (size_t)(c & 63);
            wmma::store_matrix_sync(jac + off, acc, 64, wmma::mem_row_major);
        }
    }
}

extern "C" void kernel_launch(void* const* d_in, const int* in_sizes, int n_in,
                              void* d_out, int out_size) {
    const float* x0 = (const float*)d_in[0];
    const float* v0 = (const float*)d_in[1];
    const float* W  = (const float*)d_in[2];
    float* out = (float*)d_out;
    // output = [traj (frames x N x D)] then [jac (N x D x D x D)]
    float* jac = out + ((size_t)out_size - (size_t)N * D * D * D);

    kprep<<<96, 128>>>(x0, v0, W, out);
    k4_jac<<<2048, 256>>>(jac);
}